// round 7
// baseline (speedup 1.0000x reference)
#include <cuda_runtime.h>
#include <math.h>

#define SEQ 2048
#define DM 2048
#define NH 32
#define NKV 8
#define HD 64
#define MROWS (2*SEQ)          // 4096 rows (b*s)
#define KVW (NKV*HD)           // 512

// Scratch (allocation-free rule: __device__ globals)
static __device__ float g_q[(size_t)MROWS * DM];       // 33.5 MB
static __device__ float g_k[(size_t)MROWS * KVW];      //  8.4 MB
static __device__ float g_v[(size_t)MROWS * KVW];      //  8.4 MB
static __device__ float g_att[(size_t)MROWS * DM];     // 33.5 MB

// ---------------------------------------------------------------------------
// SGEMM: C[M,N] = A[M,K] * B[N,K]^T   (A, B row-major; classic 128x128x8 tile,
// 256 threads, 8x8 accumulator per thread, float4 global loads)
// Requires M%128==0, N%128==0, K%8==0 (true for all shapes here).
// ---------------------------------------------------------------------------
__global__ __launch_bounds__(256)
void sgemm_tn(int M, int N, int K,
              const float* __restrict__ A,
              const float* __restrict__ B,
              float* __restrict__ C)
{
    const int BM = 128, BN = 128, BK = 8, TM = 8, TN = 8;
    __shared__ float As[BK][BM];
    __shared__ float Bs[BK][BN];

    int tid  = threadIdx.x;
    int bm   = blockIdx.y * BM;
    int bn   = blockIdx.x * BN;
    int tRow = (tid >> 4) * TM;      // 0..120
    int tCol = (tid & 15) * TN;      // 0..120
    int ldRow = tid >> 1;            // 0..127
    int ldCol = (tid & 1) * 4;       // 0 or 4

    const float* Ab = A + (size_t)(bm + ldRow) * K + ldCol;
    const float* Bb = B + (size_t)(bn + ldRow) * K + ldCol;

    float acc[TM][TN];
#pragma unroll
    for (int i = 0; i < TM; i++)
#pragma unroll
        for (int j = 0; j < TN; j++) acc[i][j] = 0.f;

    for (int kt = 0; kt < K; kt += BK) {
        float4 a4 = *(const float4*)(Ab + kt);
        float4 b4 = *(const float4*)(Bb + kt);
        As[ldCol + 0][ldRow] = a4.x; As[ldCol + 1][ldRow] = a4.y;
        As[ldCol + 2][ldRow] = a4.z; As[ldCol + 3][ldRow] = a4.w;
        Bs[ldCol + 0][ldRow] = b4.x; Bs[ldCol + 1][ldRow] = b4.y;
        Bs[ldCol + 2][ldRow] = b4.z; Bs[ldCol + 3][ldRow] = b4.w;
        __syncthreads();
#pragma unroll
        for (int kk = 0; kk < BK; kk++) {
            float rm[TM], rn[TN];
#pragma unroll
            for (int i = 0; i < TM; i++) rm[i] = As[kk][tRow + i];
#pragma unroll
            for (int j = 0; j < TN; j++) rn[j] = Bs[kk][tCol + j];
#pragma unroll
            for (int i = 0; i < TM; i++)
#pragma unroll
                for (int j = 0; j < TN; j++) acc[i][j] += rm[i] * rn[j];
        }
        __syncthreads();
    }

#pragma unroll
    for (int i = 0; i < TM; i++) {
#pragma unroll
        for (int j = 0; j < TN; j += 4) {
            float4 v4 = make_float4(acc[i][j], acc[i][j+1], acc[i][j+2], acc[i][j+3]);
            *(float4*)(C + (size_t)(bm + tRow + i) * N + bn + tCol + j) = v4;
        }
    }
}

// ---------------------------------------------------------------------------
// RoPE (interleaved pairs), applied in-place to q [4096, 2048] and k [4096, 512].
// Matches reference: theta_i = 10000^(-i/32), out_even = e*c - o*s, out_odd = o*c + e*s
// theta table computed in double once per block so we match JAX's fp32 theta to <=1 ulp.
// ---------------------------------------------------------------------------
__global__ void rope_kernel(float* __restrict__ q, float* __restrict__ k)
{
    __shared__ float th[32];
    int row = blockIdx.x;            // 0..4095
    int pos = row & (SEQ - 1);
    if (threadIdx.x < 32)
        th[threadIdx.x] = (float)pow(10000.0, -(double)threadIdx.x / 32.0);
    __syncthreads();

    float* qr = q + (size_t)row * DM;
    float* kr = k + (size_t)row * KVW;
    const int NPAIR = (NH + NKV) * 32;   // 1280 pairs per row
    for (int idx = threadIdx.x; idx < NPAIR; idx += blockDim.x) {
        float* base; int hp;
        if (idx < NH * 32) { base = qr; hp = idx; }
        else               { base = kr; hp = idx - NH * 32; }
        int pair = hp & 31;
        int off  = (hp >> 5) * HD + pair * 2;
        float f = (float)pos * th[pair];
        float s, c;
        sincosf(f, &s, &c);
        float a = base[off], b = base[off + 1];
        base[off]     = a * c - b * s;
        base[off + 1] = b * c + a * s;
    }
}

// ---------------------------------------------------------------------------
// Flash attention, fp32, causal, GQA (q head h uses kv head h/4).
// Block = 64 threads, each thread owns one query row (64-float q + 64-float o
// accumulator in registers). K/V tiles (64x64) and the score/prob matrix Ps
// live in shared memory. Ps is stored key-major Ps[j][t] so both the store
// (lane-consecutive) and the PV read (lane-consecutive at fixed j) are
// bank-conflict free without padding. smem = 3 * 16KB = 48KB exactly.
// ---------------------------------------------------------------------------
__global__ __launch_bounds__(64)
void attn_kernel(const float* __restrict__ Q, const float* __restrict__ K,
                 const float* __restrict__ V, float* __restrict__ O)
{
    __shared__ float Ks[64][64];
    __shared__ float Vs[64][64];
    __shared__ float Ps[64][64];

    int t   = threadIdx.x;       // query row within tile
    int qt  = blockIdx.x;        // 0..31
    int h   = blockIdx.y;        // 0..31
    int b   = blockIdx.z;        // 0..1
    int kvh = h >> 2;
    int qrow = qt * 64 + t;

    const float* qptr = Q + ((size_t)(b * SEQ + qrow)) * DM + h * HD;
    float qreg[HD];
#pragma unroll
    for (int d = 0; d < HD; d++) qreg[d] = qptr[d] * 0.125f;  // 1/sqrt(64)

    float o[HD];
#pragma unroll
    for (int d = 0; d < HD; d++) o[d] = 0.f;
    float m = -INFINITY, l = 0.f;

    const float* kb = K + (size_t)b * SEQ * KVW + kvh * HD;
    const float* vb = V + (size_t)b * SEQ * KVW + kvh * HD;

    for (int kt = 0; kt <= qt; kt++) {
        const float* kp = kb + (size_t)kt * 64 * KVW;
        const float* vp = vb + (size_t)kt * 64 * KVW;
#pragma unroll 4
        for (int r = 0; r < 64; r++) {
            Ks[r][t] = kp[r * KVW + t];
            Vs[r][t] = vp[r * KVW + t];
        }
        __syncthreads();

        // causal: on diagonal tile, key j valid iff j <= t
        int jcnt = (kt < qt) ? 64 : (t + 1);

        float tmax = -INFINITY;
        for (int j = 0; j < jcnt; j++) {
            const float4* k4 = (const float4*)Ks[j];
            float s = 0.f;
#pragma unroll
            for (int d4 = 0; d4 < 16; d4++) {
                float4 kk = k4[d4];
                s += qreg[4*d4+0] * kk.x + qreg[4*d4+1] * kk.y
                   + qreg[4*d4+2] * kk.z + qreg[4*d4+3] * kk.w;
            }
            Ps[j][t] = s;
            tmax = fmaxf(tmax, s);
        }

        float m_new = fmaxf(m, tmax);
        float alpha = __expf(m - m_new);   // exp(-inf)=0 on first tile: OK
        l *= alpha;
#pragma unroll
        for (int d = 0; d < HD; d++) o[d] *= alpha;

        for (int j = 0; j < jcnt; j++) {
            float p = __expf(Ps[j][t] - m_new);
            l += p;
            const float4* v4 = (const float4*)Vs[j];
#pragma unroll
            for (int d4 = 0; d4 < 16; d4++) {
                float4 vv = v4[d4];
                o[4*d4+0] += p * vv.x; o[4*d4+1] += p * vv.y;
                o[4*d4+2] += p * vv.z; o[4*d4+3] += p * vv.w;
            }
        }
        m = m_new;
        __syncthreads();   // protect Ks/Vs before next tile load
    }

    float inv = 1.f / l;
    float* op = O + ((size_t)(b * SEQ + qrow)) * DM + h * HD;
#pragma unroll
    for (int d = 0; d < HD; d++) op[d] = o[d] * inv;
}

// ---------------------------------------------------------------------------
// Launch: 3 projection GEMMs -> RoPE -> flash attention -> output GEMM.
// All launches on the default stream; no allocs, no syncs (graph-capturable).
// Input order per metadata: x, wq, wk, wv, wo. Output fp32 [2,2048,2048].
// ---------------------------------------------------------------------------
extern "C" void kernel_launch(void* const* d_in, const int* in_sizes, int n_in,
                              void* d_out, int out_size)
{
    const float* x  = (const float*)d_in[0];
    const float* wq = (const float*)d_in[1];
    const float* wk = (const float*)d_in[2];
    const float* wv = (const float*)d_in[3];
    const float* wo = (const float*)d_in[4];
    float* out = (float*)d_out;

    float *q, *k, *v, *att;
    cudaGetSymbolAddress((void**)&q,   g_q);
    cudaGetSymbolAddress((void**)&k,   g_k);
    cudaGetSymbolAddress((void**)&v,   g_v);
    cudaGetSymbolAddress((void**)&att, g_att);

    dim3 blk(256);
    // Q/K/V projections: C = X * W^T
    sgemm_tn<<<dim3(DM  / 128, MROWS / 128), blk>>>(MROWS, DM,  DM, x, wq, q);
    sgemm_tn<<<dim3(KVW / 128, MROWS / 128), blk>>>(MROWS, KVW, DM, x, wk, k);
    sgemm_tn<<<dim3(KVW / 128, MROWS / 128), blk>>>(MROWS, KVW, DM, x, wv, v);

    rope_kernel<<<MROWS, 256>>>(q, k);

    attn_kernel<<<dim3(SEQ / 64, NH, 2), 64>>>(q, k, v, att);

    // Output projection: out = att * wo^T
    sgemm_tn<<<dim3(DM / 128, MROWS / 128), blk>>>(MROWS, DM, DM, att, wo, out);
}

// round 8
// speedup vs baseline: 1.0091x; 1.0091x over previous
#include <cuda_runtime.h>
#include <math.h>

#define SEQ 2048
#define DM 2048
#define NH 32
#define NKV 8
#define HD 64
#define MROWS (2*SEQ)          // 4096 rows (b*s)
#define KVW (NKV*HD)           // 512

// Scratch (allocation-free rule: __device__ globals)
static __device__ float g_q[(size_t)MROWS * DM];       // 33.5 MB
static __device__ float g_k[(size_t)MROWS * KVW];      //  8.4 MB
static __device__ float g_v[(size_t)MROWS * KVW];      //  8.4 MB
static __device__ float g_att[(size_t)MROWS * DM];     // 33.5 MB

// ---------------------------------------------------------------------------
// SGEMM: C[M,N] = A[M,K] * B[N,K]^T   (A, B row-major; classic 128x128x8 tile,
// 256 threads, 8x8 accumulator per thread, float4 global loads)
// Requires M%128==0, N%128==0, K%8==0 (true for all shapes here).
// ---------------------------------------------------------------------------
__global__ __launch_bounds__(256)
void sgemm_tn(int M, int N, int K,
              const float* __restrict__ A,
              const float* __restrict__ B,
              float* __restrict__ C)
{
    const int BM = 128, BN = 128, BK = 8, TM = 8, TN = 8;
    __shared__ float As[BK][BM];
    __shared__ float Bs[BK][BN];

    int tid  = threadIdx.x;
    int bm   = blockIdx.y * BM;
    int bn   = blockIdx.x * BN;
    int tRow = (tid >> 4) * TM;      // 0..120
    int tCol = (tid & 15) * TN;      // 0..120
    int ldRow = tid >> 1;            // 0..127
    int ldCol = (tid & 1) * 4;       // 0 or 4

    const float* Ab = A + (size_t)(bm + ldRow) * K + ldCol;
    const float* Bb = B + (size_t)(bn + ldRow) * K + ldCol;

    float acc[TM][TN];
#pragma unroll
    for (int i = 0; i < TM; i++)
#pragma unroll
        for (int j = 0; j < TN; j++) acc[i][j] = 0.f;

    for (int kt = 0; kt < K; kt += BK) {
        float4 a4 = *(const float4*)(Ab + kt);
        float4 b4 = *(const float4*)(Bb + kt);
        As[ldCol + 0][ldRow] = a4.x; As[ldCol + 1][ldRow] = a4.y;
        As[ldCol + 2][ldRow] = a4.z; As[ldCol + 3][ldRow] = a4.w;
        Bs[ldCol + 0][ldRow] = b4.x; Bs[ldCol + 1][ldRow] = b4.y;
        Bs[ldCol + 2][ldRow] = b4.z; Bs[ldCol + 3][ldRow] = b4.w;
        __syncthreads();
#pragma unroll
        for (int kk = 0; kk < BK; kk++) {
            float rm[TM], rn[TN];
#pragma unroll
            for (int i = 0; i < TM; i++) rm[i] = As[kk][tRow + i];
#pragma unroll
            for (int j = 0; j < TN; j++) rn[j] = Bs[kk][tCol + j];
#pragma unroll
            for (int i = 0; i < TM; i++)
#pragma unroll
                for (int j = 0; j < TN; j++) acc[i][j] += rm[i] * rn[j];
        }
        __syncthreads();
    }

#pragma unroll
    for (int i = 0; i < TM; i++) {
#pragma unroll
        for (int j = 0; j < TN; j += 4) {
            float4 v4 = make_float4(acc[i][j], acc[i][j+1], acc[i][j+2], acc[i][j+3]);
            *(float4*)(C + (size_t)(bm + tRow + i) * N + bn + tCol + j) = v4;
        }
    }
}

// ---------------------------------------------------------------------------
// RoPE (interleaved pairs), applied in-place to q [4096, 2048] and k [4096, 512].
// Matches reference: theta_i = 10000^(-i/32), out_even = e*c - o*s, out_odd = o*c + e*s
// theta table computed in double once per block so we match JAX's fp32 theta to <=1 ulp.
// ---------------------------------------------------------------------------
__global__ void rope_kernel(float* __restrict__ q, float* __restrict__ k)
{
    __shared__ float th[32];
    int row = blockIdx.x;            // 0..4095
    int pos = row & (SEQ - 1);
    if (threadIdx.x < 32)
        th[threadIdx.x] = (float)pow(10000.0, -(double)threadIdx.x / 32.0);
    __syncthreads();

    float* qr = q + (size_t)row * DM;
    float* kr = k + (size_t)row * KVW;
    const int NPAIR = (NH + NKV) * 32;   // 1280 pairs per row
    for (int idx = threadIdx.x; idx < NPAIR; idx += blockDim.x) {
        float* base; int hp;
        if (idx < NH * 32) { base = qr; hp = idx; }
        else               { base = kr; hp = idx - NH * 32; }
        int pair = hp & 31;
        int off  = (hp >> 5) * HD + pair * 2;
        float f = (float)pos * th[pair];
        float s, c;
        sincosf(f, &s, &c);
        float a = base[off], b = base[off + 1];
        base[off]     = a * c - b * s;
        base[off + 1] = b * c + a * s;
    }
}

// ---------------------------------------------------------------------------
// Flash attention, fp32, causal, GQA (q head h uses kv head h/4).
// Block = 64 threads, each thread owns one query row (64-float q + 64-float o
// accumulator in registers). K/V tiles (64x64) and the score/prob matrix Ps
// live in shared memory. Ps is stored key-major Ps[j][t] so both the store
// (lane-consecutive) and the PV read (lane-consecutive at fixed j) are
// bank-conflict free without padding. smem = 3 * 16KB = 48KB exactly.
// ---------------------------------------------------------------------------
__global__ __launch_bounds__(64)
void attn_kernel(const float* __restrict__ Q, const float* __restrict__ K,
                 const float* __restrict__ V, float* __restrict__ O)
{
    __shared__ float Ks[64][64];
    __shared__ float Vs[64][64];
    __shared__ float Ps[64][64];

    int t   = threadIdx.x;       // query row within tile
    int qt  = blockIdx.x;        // 0..31
    int h   = blockIdx.y;        // 0..31
    int b   = blockIdx.z;        // 0..1
    int kvh = h >> 2;
    int qrow = qt * 64 + t;

    const float* qptr = Q + ((size_t)(b * SEQ + qrow)) * DM + h * HD;
    float qreg[HD];
#pragma unroll
    for (int d = 0; d < HD; d++) qreg[d] = qptr[d] * 0.125f;  // 1/sqrt(64)

    float o[HD];
#pragma unroll
    for (int d = 0; d < HD; d++) o[d] = 0.f;
    float m = -INFINITY, l = 0.f;

    const float* kb = K + (size_t)b * SEQ * KVW + kvh * HD;
    const float* vb = V + (size_t)b * SEQ * KVW + kvh * HD;

    for (int kt = 0; kt <= qt; kt++) {
        const float* kp = kb + (size_t)kt * 64 * KVW;
        const float* vp = vb + (size_t)kt * 64 * KVW;
#pragma unroll 4
        for (int r = 0; r < 64; r++) {
            Ks[r][t] = kp[r * KVW + t];
            Vs[r][t] = vp[r * KVW + t];
        }
        __syncthreads();

        // causal: on diagonal tile, key j valid iff j <= t
        int jcnt = (kt < qt) ? 64 : (t + 1);

        float tmax = -INFINITY;
        for (int j = 0; j < jcnt; j++) {
            const float4* k4 = (const float4*)Ks[j];
            float s = 0.f;
#pragma unroll
            for (int d4 = 0; d4 < 16; d4++) {
                float4 kk = k4[d4];
                s += qreg[4*d4+0] * kk.x + qreg[4*d4+1] * kk.y
                   + qreg[4*d4+2] * kk.z + qreg[4*d4+3] * kk.w;
            }
            Ps[j][t] = s;
            tmax = fmaxf(tmax, s);
        }

        float m_new = fmaxf(m, tmax);
        float alpha = __expf(m - m_new);   // exp(-inf)=0 on first tile: OK
        l *= alpha;
#pragma unroll
        for (int d = 0; d < HD; d++) o[d] *= alpha;

        for (int j = 0; j < jcnt; j++) {
            float p = __expf(Ps[j][t] - m_new);
            l += p;
            const float4* v4 = (const float4*)Vs[j];
#pragma unroll
            for (int d4 = 0; d4 < 16; d4++) {
                float4 vv = v4[d4];
                o[4*d4+0] += p * vv.x; o[4*d4+1] += p * vv.y;
                o[4*d4+2] += p * vv.z; o[4*d4+3] += p * vv.w;
            }
        }
        m = m_new;
        __syncthreads();   // protect Ks/Vs before next tile load
    }

    float inv = 1.f / l;
    float* op = O + ((size_t)(b * SEQ + qrow)) * DM + h * HD;
#pragma unroll
    for (int d = 0; d < HD; d++) op[d] = o[d] * inv;
}

// ---------------------------------------------------------------------------
// Launch: 3 projection GEMMs -> RoPE -> flash attention -> output GEMM.
// All launches on the default stream; no allocs, no syncs (graph-capturable).
// Input order per metadata: x, wq, wk, wv, wo. Output fp32 [2,2048,2048].
// ---------------------------------------------------------------------------
extern "C" void kernel_launch(void* const* d_in, const int* in_sizes, int n_in,
                              void* d_out, int out_size)
{
    const float* x  = (const float*)d_in[0];
    const float* wq = (const float*)d_in[1];
    const float* wk = (const float*)d_in[2];
    const float* wv = (const float*)d_in[3];
    const float* wo = (const float*)d_in[4];
    float* out = (float*)d_out;

    float *q, *k, *v, *att;
    cudaGetSymbolAddress((void**)&q,   g_q);
    cudaGetSymbolAddress((void**)&k,   g_k);
    cudaGetSymbolAddress((void**)&v,   g_v);
    cudaGetSymbolAddress((void**)&att, g_att);

    dim3 blk(256);
    // Q/K/V projections: C = X * W^T
    sgemm_tn<<<dim3(DM  / 128, MROWS / 128), blk>>>(MROWS, DM,  DM, x, wq, q);
    sgemm_tn<<<dim3(KVW / 128, MROWS / 128), blk>>>(MROWS, KVW, DM, x, wk, k);
    sgemm_tn<<<dim3(KVW / 128, MROWS / 128), blk>>>(MROWS, KVW, DM, x, wv, v);

    rope_kernel<<<MROWS, 256>>>(q, k);

    attn_kernel<<<dim3(SEQ / 64, NH, 2), 64>>>(q, k, v, att);

    // Output projection: out = att * wo^T
    sgemm_tn<<<dim3(DM / 128, MROWS / 128), blk>>>(MROWS, DM, DM, att, wo, out);
}